// round 3
// baseline (speedup 1.0000x reference)
#include <cuda_runtime.h>
#include <math.h>

#define NH   64
#define NI   128
#define NHID 512
#define NO   256
#define NS   4
#define EPS_GN 1e-5f
#define TINY 1e-14f

// ---------------- scratch (device globals: no allocation allowed) ----------
__device__ float g_sub[NH * NI];        // (H, n_inp)
__device__ float g_lastprod[NO];        // (n_out,)
__device__ float g_h1[NH * NHID];       // (H, n_hid)
__device__ float g_psm[NS * NH * NO];   // per-s softmax results
__device__ float g_scalar[NH * NO];     // ws row sums

// ---------------- reductions ----------------
__device__ __forceinline__ float warp_sum(float v) {
#pragma unroll
    for (int o = 16; o > 0; o >>= 1) v += __shfl_xor_sync(0xffffffffu, v, o);
    return v;
}
__device__ __forceinline__ float warp_max(float v) {
#pragma unroll
    for (int o = 16; o > 0; o >>= 1) v = fmaxf(v, __shfl_xor_sync(0xffffffffu, v, o));
    return v;
}

// Block-wide sum/max. NW = number of warps in the block. Safe for repeated
// calls on the same `red` buffer (leading barrier protects prior readers).
template <int NW>
__device__ __forceinline__ float block_sum(float v, float* red, int tid) {
    v = warp_sum(v);
    __syncthreads();
    if ((tid & 31) == 0) red[tid >> 5] = v;
    __syncthreads();
    float s = 0.f;
#pragma unroll
    for (int i = 0; i < NW; i++) s += red[i];
    return s;
}
template <int NW>
__device__ __forceinline__ float block_max(float v, float* red, int tid) {
    v = warp_max(v);
    __syncthreads();
    if ((tid & 31) == 0) red[tid >> 5] = v;
    __syncthreads();
    float s = -INFINITY;
#pragma unroll
    for (int i = 0; i < NW; i++) s = fmaxf(s, red[i]);
    return s;
}

// ---------------- k0: sub = einsum("rc,hc->hr", x, qw); last_prod ----------
// grid 65 x 128 threads. Blocks 0..63: head h. Block 64: last_prod.
__global__ void k0_sub(const float* __restrict__ x,
                       const float* __restrict__ qw,
                       const float* __restrict__ lsm) {
    if (blockIdx.x == NH) {
        for (int o = threadIdx.x; o < NO; o += blockDim.x) {
            float p = 1.f;
#pragma unroll 8
            for (int k = 0; k < NH; k++) p *= lsm[o * NH + k];
            g_lastprod[o] = p;
        }
        return;
    }
    const int h = blockIdx.x;
    __shared__ float s_qw[NI];
    const int tid = threadIdx.x;
    if (tid < NI) s_qw[tid] = qw[h * NI + tid];
    __syncthreads();
    const int warp = tid >> 5, lane = tid & 31;
    const float4 qv = ((const float4*)s_qw)[lane];
    for (int r = warp; r < NI; r += 4) {
        float4 xv = __ldg((const float4*)(x + (size_t)r * NI) + lane);
        float v = xv.x * qv.x + xv.y * qv.y + xv.z * qv.z + xv.w * qv.w;
        v = warp_sum(v);
        if (lane == 0) g_sub[h * NI + r] = v;
    }
}

// ---------------- k1: h1 = softplus(GN(w1 @ sub)) -------------------------
// grid 64 (head) x 512 threads (16 warps x 32 rows of length 128).
__global__ void k1_h1(const float* __restrict__ w1,
                      const float* __restrict__ g1,
                      const float* __restrict__ b1) {
    const int h = blockIdx.x, tid = threadIdx.x;
    const int warp = tid >> 5, lane = tid & 31;
    __shared__ float s_sub[NI];
    __shared__ float s_t1[NHID];
    __shared__ float red[16];
    if (tid < NI) s_sub[tid] = g_sub[h * NI + tid];
    __syncthreads();
    const float4 sv = ((const float4*)s_sub)[lane];
    const float4* wbase = (const float4*)(w1 + (size_t)h * NHID * NI);
    for (int j = 0; j < 32; j += 4) {
        float4 wv[4];
#pragma unroll
        for (int u = 0; u < 4; u++) {
            int o = warp + (j + u) * 16;
            wv[u] = __ldg(wbase + (size_t)o * (NI / 4) + lane);
        }
#pragma unroll
        for (int u = 0; u < 4; u++) {
            int o = warp + (j + u) * 16;
            float v = wv[u].x * sv.x + wv[u].y * sv.y + wv[u].z * sv.z + wv[u].w * sv.w;
            v = warp_sum(v);
            if (lane == 0) s_t1[o] = v;
        }
    }
    __syncthreads();
    const float t = s_t1[tid];
    const float mu = block_sum<16>(t, red, tid) * (1.f / NHID);
    const float d = t - mu;
    const float var = block_sum<16>(d * d, red, tid) * (1.f / NHID);
    const float zn = d * rsqrtf(var + EPS_GN) * g1[h * NHID + tid] + b1[h * NHID + tid];
    // stable softplus
    g_h1[h * NHID + tid] = fmaxf(zn, 0.f) + log1pf(expf(-fabsf(zn)));
}

// ---------------- k2: z = GN(w2 @ h1); softmax per (s,h) -------------------
// grid 256 = (s*64+h), 512 threads (16 warps x 16 rows of length 512).
__global__ void k2_z(const float* __restrict__ w2,
                     const float* __restrict__ g2,
                     const float* __restrict__ b2) {
    const int b = blockIdx.x;             // b = s*64 + h
    const int h = b & 63;
    const int tid = threadIdx.x, warp = tid >> 5, lane = tid & 31;
    __shared__ float s_h1[NHID];
    __shared__ float s_z[NO];
    __shared__ float red[16];
    s_h1[tid] = g_h1[h * NHID + tid];
    __syncthreads();
    float4 hv[4];
#pragma unroll
    for (int k = 0; k < 4; k++) hv[k] = ((const float4*)s_h1)[k * 32 + lane];
    const float4* wbase = (const float4*)(w2 + (size_t)b * NO * NHID);
    for (int j = 0; j < 16; j += 2) {
        float4 wv[2][4];
#pragma unroll
        for (int u = 0; u < 2; u++) {
            int o = warp + (j + u) * 16;
            const float4* row = wbase + (size_t)o * (NHID / 4);
#pragma unroll
            for (int k = 0; k < 4; k++) wv[u][k] = __ldg(row + k * 32 + lane);
        }
#pragma unroll
        for (int u = 0; u < 2; u++) {
            float v = 0.f;
#pragma unroll
            for (int k = 0; k < 4; k++)
                v += wv[u][k].x * hv[k].x + wv[u][k].y * hv[k].y +
                     wv[u][k].z * hv[k].z + wv[u][k].w * hv[k].w;
            v = warp_sum(v);
            if (lane == 0) s_z[warp + (j + u) * 16] = v;
        }
    }
    __syncthreads();
    const bool act = tid < NO;
    const float z = act ? s_z[tid] : 0.f;
    const float mu = block_sum<16>(z, red, tid) * (1.f / NO);
    const float d = act ? (z - mu) : 0.f;
    const float var = block_sum<16>(d * d, red, tid) * (1.f / NO);
    float zn = 0.f;
    if (act) zn = d * rsqrtf(var + EPS_GN) * g2[b * NO + tid] + b2[b * NO + tid];
    const float mx = block_max<16>(act ? zn : -INFINITY, red, tid);
    const float e = act ? expf(zn - mx) : 0.f;
    const float esum = block_sum<16>(e, red, tid);
    if (act) g_psm[b * NO + tid] = e / esum;
}

// ---------------- k3: scalar = ws.sum(-1) ---------------------------------
// warp-per-row, 2 float4/lane per row of 256.
__global__ void k3_scalar(const float* __restrict__ ws) {
    const int gw = (blockIdx.x * blockDim.x + threadIdx.x) >> 5;
    const int lane = threadIdx.x & 31;
    const int nw = (gridDim.x * blockDim.x) >> 5;
    for (int row = gw; row < NH * NO; row += nw) {
        const float4* r = (const float4*)(ws + (size_t)row * NO);
        float4 a = __ldg(r + lane), c = __ldg(r + 32 + lane);
        float v = a.x + a.y + a.z + a.w + c.x + c.y + c.z + c.w;
        v = warp_sum(v);
        if (lane == 0) g_scalar[row] = v;
    }
}

// ---------------- k4: gate + outputs --------------------------------------
// grid 64 (head) x 256 threads (one per n_out position).
__global__ void k4_final(const float* __restrict__ woo, float* __restrict__ out) {
    const int h = blockIdx.x, o = threadIdx.x;
    __shared__ float red[8];
    float osm = 0.f;
#pragma unroll
    for (int s = 0; s < NS; s++) osm += g_psm[(s * NH + h) * NO + o];
    const float part = woo[h * 2 * NO + o] * g_lastprod[o] +
                       woo[h * 2 * NO + NO + o] * osm;
    const float logit = block_sum<8>(part, red, o);
    const float on = 1.f / (1.f + expf(-logit));
    const float a = on * osm;
    out[o * NH + h] = fmaxf(a, TINY);                 // clip(on_off*out_sm, TINY, None)
    float v = a * g_scalar[h * NO + o];
    out[NO * NH + o * NH + h] = (fabsf(v) <= TINY) ? TINY : v;
}

// ---------------- launch ---------------------------------------------------
extern "C" void kernel_launch(void* const* d_in, const int* in_sizes, int n_in,
                              void* d_out, int out_size) {
    const float* x   = (const float*)d_in[0];
    const float* lsm = (const float*)d_in[1];
    const float* qw  = (const float*)d_in[2];
    const float* w1  = (const float*)d_in[3];
    const float* g1  = (const float*)d_in[4];
    const float* b1  = (const float*)d_in[5];
    const float* w2  = (const float*)d_in[6];
    const float* g2  = (const float*)d_in[7];
    const float* b2  = (const float*)d_in[8];
    const float* ws  = (const float*)d_in[9];
    const float* woo = (const float*)d_in[10];
    float* out = (float*)d_out;

    k0_sub<<<NH + 1, 128>>>(x, qw, lsm);
    k1_h1<<<NH, 512>>>(w1, g1, b1);
    k2_z<<<NS * NH, 512>>>(w2, g2, b2);
    k3_scalar<<<256, 256>>>(ws);
    k4_final<<<NH, 256>>>(woo, out);
}

// round 4
// speedup vs baseline: 1.0131x; 1.0131x over previous
#include <cuda_runtime.h>
#include <math.h>

#define NH   64
#define NI   128
#define NHID 512
#define NO   256
#define NS   4
#define EPS_GN 1e-5f
#define TINY 1e-14f

// ---------------- scratch (device globals: no allocation allowed) ----------
__device__ float g_sub[NH * NI];        // (H, n_inp)
__device__ float g_lastprod[NO];        // (n_out,)
__device__ float g_t1[NH * NHID];       // raw w1@sub, pre-GN
__device__ float g_h1[NH * NHID];       // softplus(GN(t1))
__device__ float g_z[NS * NH * NO];     // raw w2@h1, pre-GN
__device__ float g_scalar[NH * NO];     // ws row sums

// ---------------- reductions ----------------
__device__ __forceinline__ float warp_sum(float v) {
#pragma unroll
    for (int o = 16; o > 0; o >>= 1) v += __shfl_xor_sync(0xffffffffu, v, o);
    return v;
}
__device__ __forceinline__ float warp_max(float v) {
#pragma unroll
    for (int o = 16; o > 0; o >>= 1) v = fmaxf(v, __shfl_xor_sync(0xffffffffu, v, o));
    return v;
}
template <int NW>
__device__ __forceinline__ float block_sum(float v, float* red, int tid) {
    v = warp_sum(v);
    __syncthreads();
    if ((tid & 31) == 0) red[tid >> 5] = v;
    __syncthreads();
    float s = 0.f;
#pragma unroll
    for (int i = 0; i < NW; i++) s += red[i];
    return s;
}
template <int NW>
__device__ __forceinline__ float block_max(float v, float* red, int tid) {
    v = warp_max(v);
    __syncthreads();
    if ((tid & 31) == 0) red[tid >> 5] = v;
    __syncthreads();
    float s = -INFINITY;
#pragma unroll
    for (int i = 0; i < NW; i++) s = fmaxf(s, red[i]);
    return s;
}

// ---------------- kA: sub + last_prod + ws row sums ------------------------
// grid 321 x 256. Blocks 0..63: sub per head. Block 64: last_prod.
// Blocks 65..320: ws row-sum chunks (2048 warps x 8 contiguous rows).
__global__ void kA(const float* __restrict__ x,
                   const float* __restrict__ qw,
                   const float* __restrict__ lsm,
                   const float* __restrict__ ws) {
    const int tid = threadIdx.x, warp = tid >> 5, lane = tid & 31;
    if (blockIdx.x < NH) {
        const int h = blockIdx.x;
        __shared__ float s_qw[NI];
        if (tid < NI) s_qw[tid] = qw[h * NI + tid];
        __syncthreads();
        const float4 qv = ((const float4*)s_qw)[lane];
        for (int r = warp; r < NI; r += 8) {
            float4 xv = __ldg((const float4*)(x + (size_t)r * NI) + lane);
            float v = xv.x * qv.x + xv.y * qv.y + xv.z * qv.z + xv.w * qv.w;
            v = warp_sum(v);
            if (lane == 0) g_sub[h * NI + r] = v;
        }
    } else if (blockIdx.x == NH) {
        const int o = tid;  // 256 threads, one per n_out
        float p = 1.f;
#pragma unroll 8
        for (int k = 0; k < NH; k++) p *= lsm[o * NH + k];
        g_lastprod[o] = p;
    } else {
        // ws: (NH*NO) rows of NO floats (1 KB). Warp-per-8-row chunk.
        const int w = (blockIdx.x - NH - 1) * 8 + warp;   // 0..2047
        const int row0 = w * 8;
        const float4* base = (const float4*)ws + (size_t)row0 * (NO / 4);
#pragma unroll
        for (int j = 0; j < 8; j += 4) {
            float4 a[4][2];
#pragma unroll
            for (int u = 0; u < 4; u++) {
                a[u][0] = __ldg(base + (size_t)(j + u) * (NO / 4) + lane);
                a[u][1] = __ldg(base + (size_t)(j + u) * (NO / 4) + 32 + lane);
            }
#pragma unroll
            for (int u = 0; u < 4; u++) {
                float v = a[u][0].x + a[u][0].y + a[u][0].z + a[u][0].w +
                          a[u][1].x + a[u][1].y + a[u][1].z + a[u][1].w;
                v = warp_sum(v);
                if (lane == 0) g_scalar[row0 + j + u] = v;
            }
        }
    }
}

// ---------------- kB: t1 = w1 @ sub (flat rows) ----------------------------
// 32768 rows of 128 floats. grid 256 x 256: 2048 warps x 16-row chunks
// (16 divides 512, so a warp's chunk stays within one head).
__global__ void kB(const float* __restrict__ w1) {
    const int tid = threadIdx.x, warp = tid >> 5, lane = tid & 31;
    const int w = blockIdx.x * 8 + warp;      // 0..2047
    const int row0 = w * 16;
    const int h = row0 >> 9;                  // /512
    const float4 sv = ((const float4*)(g_sub + h * NI))[lane];
    const float4* base = (const float4*)w1 + (size_t)row0 * (NI / 4);
#pragma unroll
    for (int j = 0; j < 16; j += 4) {
        float4 a[4];
#pragma unroll
        for (int u = 0; u < 4; u++)
            a[u] = __ldg(base + (size_t)(j + u) * (NI / 4) + lane);
#pragma unroll
        for (int u = 0; u < 4; u++) {
            float v = a[u].x * sv.x + a[u].y * sv.y + a[u].z * sv.z + a[u].w * sv.w;
            v = warp_sum(v);
            if (lane == 0) g_t1[row0 + j + u] = v;
        }
    }
}

// ---------------- kB2: h1 = softplus(GN(t1)) -------------------------------
// grid 64 x 512 (L2-resident, tiny).
__global__ void kB2(const float* __restrict__ g1, const float* __restrict__ b1) {
    const int h = blockIdx.x, tid = threadIdx.x;
    __shared__ float red[16];
    const float t = g_t1[h * NHID + tid];
    const float mu = block_sum<16>(t, red, tid) * (1.f / NHID);
    const float d = t - mu;
    const float var = block_sum<16>(d * d, red, tid) * (1.f / NHID);
    const float zn = d * rsqrtf(var + EPS_GN) * g1[h * NHID + tid] + b1[h * NHID + tid];
    g_h1[h * NHID + tid] = fmaxf(zn, 0.f) + log1pf(expf(-fabsf(zn)));   // stable softplus
}

// ---------------- kC: z = w2 @ h1 (flat rows, the 128 MB stream) -----------
// 65536 rows of 512 floats (2 KB). grid 1024 x 256: 8192 warps x 8-row chunks.
// A chunk never crosses a (s,h) boundary (8 | 256), so h1 loads once per warp.
__global__ void kC(const float* __restrict__ w2) {
    const int tid = threadIdx.x, warp = tid >> 5, lane = tid & 31;
    const int c = blockIdx.x * 8 + warp;      // 0..8191
    const int row0 = c * 8;
    const int b = row0 >> 8;                  // s*64+h
    const int h = b & 63;
    float4 hv[4];
    const float4* hb = (const float4*)(g_h1 + h * NHID);
#pragma unroll
    for (int k = 0; k < 4; k++) hv[k] = hb[k * 32 + lane];
    const float4* base = (const float4*)w2 + (size_t)row0 * (NHID / 4);
#pragma unroll
    for (int j = 0; j < 8; j += 2) {
        float4 a[2][4];
#pragma unroll
        for (int u = 0; u < 2; u++)
#pragma unroll
            for (int k = 0; k < 4; k++)
                a[u][k] = __ldg(base + (size_t)(j + u) * (NHID / 4) + k * 32 + lane);
#pragma unroll
        for (int u = 0; u < 2; u++) {
            float v = 0.f;
#pragma unroll
            for (int k = 0; k < 4; k++)
                v += a[u][k].x * hv[k].x + a[u][k].y * hv[k].y +
                     a[u][k].z * hv[k].z + a[u][k].w * hv[k].w;
            v = warp_sum(v);
            if (lane == 0) g_z[row0 + j + u] = v;
        }
    }
}

// ---------------- kD: GN + softmax + gate + outputs ------------------------
// grid 64 (head) x 256 (one thread per n_out position, all 4 s values).
__global__ void kD(const float* __restrict__ g2, const float* __restrict__ b2,
                   const float* __restrict__ woo, float* __restrict__ out) {
    const int h = blockIdx.x, o = threadIdx.x;
    __shared__ float red[8];
    float osm = 0.f;
#pragma unroll
    for (int s = 0; s < NS; s++) {
        const int b = s * NH + h;
        const float z = g_z[b * NO + o];
        const float mu = block_sum<8>(z, red, o) * (1.f / NO);
        const float d = z - mu;
        const float var = block_sum<8>(d * d, red, o) * (1.f / NO);
        const float zn = d * rsqrtf(var + EPS_GN) * g2[b * NO + o] + b2[b * NO + o];
        const float mx = block_max<8>(zn, red, o);
        const float e = expf(zn - mx);
        const float es = block_sum<8>(e, red, o);
        osm += e / es;
    }
    const float part = woo[h * 2 * NO + o] * g_lastprod[o] +
                       woo[h * 2 * NO + NO + o] * osm;
    const float logit = block_sum<8>(part, red, o);
    const float on = 1.f / (1.f + expf(-logit));
    const float a = on * osm;
    out[o * NH + h] = fmaxf(a, TINY);                 // clip(on_off*out_sm, TINY, None)
    float v = a * g_scalar[h * NO + o];
    out[NO * NH + o * NH + h] = (fabsf(v) <= TINY) ? TINY : v;
}

// ---------------- launch ---------------------------------------------------
extern "C" void kernel_launch(void* const* d_in, const int* in_sizes, int n_in,
                              void* d_out, int out_size) {
    const float* x   = (const float*)d_in[0];
    const float* lsm = (const float*)d_in[1];
    const float* qw  = (const float*)d_in[2];
    const float* w1  = (const float*)d_in[3];
    const float* g1  = (const float*)d_in[4];
    const float* b1  = (const float*)d_in[5];
    const float* w2  = (const float*)d_in[6];
    const float* g2  = (const float*)d_in[7];
    const float* b2  = (const float*)d_in[8];
    const float* ws  = (const float*)d_in[9];
    const float* woo = (const float*)d_in[10];
    float* out = (float*)d_out;

    kA<<<NH + 1 + 256, 256>>>(x, qw, lsm, ws);   // sub + last_prod + ws sums
    kB<<<256, 256>>>(w1);                        // t1
    kB2<<<NH, 512>>>(g1, b1);                    // h1
    kC<<<1024, 256>>>(w2);                       // z  (dominant 128 MB stream)
    kD<<<NH, 256>>>(g2, b2, woo, out);           // GN+softmax+gate+outputs
}